// round 1
// baseline (speedup 1.0000x reference)
#include <cuda_runtime.h>
#include <math.h>

#define LSEQ   4096
#define DCH    768
#define NBATCH 8
#define NBLK   8
#define BS     96
#define NMODES 2049   // LSEQ/2 + 1
#define MP     2064   // padded mode stride
#define MT     64     // mode tile in MLP kernel
#define LAMBDA 0.01f

// Scratch spectra: (B, D, MP) real and imag, ~50.7MB each (static device arrays: allowed)
__device__ float g_Sr[(size_t)NBATCH * DCH * MP];
__device__ float g_Si[(size_t)NBATCH * DCH * MP];

// ---------------------------------------------------------------------------
// Forward FFT: one CTA per (batch, channel-pair). Real-pair trick:
// z = x[:,d0] + i x[:,d1]; after FFT, separate Hermitian components.
// Stockham radix-2 DIF, self-sorting, 12 stages, twiddle table in smem.
// ---------------------------------------------------------------------------
extern __shared__ char smem_raw[];

__global__ __launch_bounds__(256) void fwd_fft_kernel(const float* __restrict__ x) {
    float2* bufA = reinterpret_cast<float2*>(smem_raw);
    float2* bufB = bufA + LSEQ;
    float2* tw   = bufB + LSEQ;          // 2048 roots e^{-2pi i j / 4096}
    const int tid = threadIdx.x;
    const int T   = 256;
    const int bi  = blockIdx.x;
    const int b   = bi / (DCH / 2);
    const int d0  = (bi % (DCH / 2)) * 2;

    for (int j = tid; j < LSEQ / 2; j += T) {
        float sv, cv;
        sincosf(-6.28318530717958647692f * (float)j / (float)LSEQ, &sv, &cv);
        tw[j] = make_float2(cv, sv);
    }
    const float* xb = x + (size_t)b * LSEQ * DCH + d0;
    for (int l = tid; l < LSEQ; l += T) {
        bufA[l] = *reinterpret_cast<const float2*>(xb + (size_t)l * DCH);
    }
    __syncthreads();

    float2* src = bufA;
    float2* dst = bufB;
    for (int ls = 0; ls < 12; ls++) {
        const int s = 1 << ls;
        for (int t = tid; t < LSEQ / 2; t += T) {
            float2 a = src[t];
            float2 c = src[t + LSEQ / 2];
            float2 w = tw[t & ~(s - 1)];        // = e^{-2pi i p / n}, p = t>>ls
            float dx = a.x - c.x, dy = a.y - c.y;
            int o = t + (t & ~(s - 1));         // q + 2*s*p
            dst[o]     = make_float2(a.x + c.x, a.y + c.y);
            dst[o + s] = make_float2(dx * w.x - dy * w.y, dx * w.y + dy * w.x);
        }
        __syncthreads();
        float2* tmp = src; src = dst; dst = tmp;
    }
    // result in src (== bufA after 12 swaps), natural order.
    // Separate pair: A[k] = (Z[k]+conj(Z[N-k]))/2 ; B[k] = (Z[k]-conj(Z[N-k]))/(2i)
    // ortho norm: * 1/sqrt(4096) = 1/64
    const float scale = 0.5f / 64.0f;
    float* SrB = g_Sr + ((size_t)b * DCH + d0) * MP;
    float* SiB = g_Si + ((size_t)b * DCH + d0) * MP;
    for (int k = tid; k < NMODES; k += T) {
        float2 z1 = src[k];
        float2 z2 = src[(LSEQ - k) & (LSEQ - 1)];
        SrB[k]      = (z1.x + z2.x) * scale;   // Re A
        SiB[k]      = (z1.y - z2.y) * scale;   // Im A
        SrB[MP + k] = (z1.y + z2.y) * scale;   // Re B
        SiB[MP + k] = (z2.x - z1.x) * scale;   // Im B
    }
}

// ---------------------------------------------------------------------------
// Inverse FFT: rebuild full spectrum Z[k] = A[k] + i B[k] (Hermitian extension),
// inverse transform (conj twiddles), re -> channel d0, im -> d1, add residual.
// Imag of DC and Nyquist bins is ignored (matches irfft semantics).
// ---------------------------------------------------------------------------
__global__ __launch_bounds__(256) void inv_fft_kernel(const float* __restrict__ x,
                                                      float* __restrict__ y) {
    float2* bufA = reinterpret_cast<float2*>(smem_raw);
    float2* bufB = bufA + LSEQ;
    float2* tw   = bufB + LSEQ;
    const int tid = threadIdx.x;
    const int T   = 256;
    const int bi  = blockIdx.x;
    const int b   = bi / (DCH / 2);
    const int d0  = (bi % (DCH / 2)) * 2;

    for (int j = tid; j < LSEQ / 2; j += T) {
        float sv, cv;
        sincosf(6.28318530717958647692f * (float)j / (float)LSEQ, &sv, &cv);
        tw[j] = make_float2(cv, sv);
    }
    const float* SrB = g_Sr + ((size_t)b * DCH + d0) * MP;
    const float* SiB = g_Si + ((size_t)b * DCH + d0) * MP;
    for (int k = tid; k < NMODES; k += T) {
        float ar  = SrB[k],      ai  = SiB[k];
        float br  = SrB[MP + k], bi_ = SiB[MP + k];
        if (k == 0 || k == LSEQ / 2) { ai = 0.0f; bi_ = 0.0f; }
        bufA[k] = make_float2(ar - bi_, ai + br);
        if (k > 0 && k < LSEQ / 2)
            bufA[LSEQ - k] = make_float2(ar + bi_, br - ai);  // conj extension
    }
    __syncthreads();

    float2* src = bufA;
    float2* dst = bufB;
    for (int ls = 0; ls < 12; ls++) {
        const int s = 1 << ls;
        for (int t = tid; t < LSEQ / 2; t += T) {
            float2 a = src[t];
            float2 c = src[t + LSEQ / 2];
            float2 w = tw[t & ~(s - 1)];
            float dx = a.x - c.x, dy = a.y - c.y;
            int o = t + (t & ~(s - 1));
            dst[o]     = make_float2(a.x + c.x, a.y + c.y);
            dst[o + s] = make_float2(dx * w.x - dy * w.y, dx * w.y + dy * w.x);
        }
        __syncthreads();
        float2* tmp = src; src = dst; dst = tmp;
    }
    const float scale = 1.0f / 64.0f;   // ortho inverse
    const float* xb = x + (size_t)b * LSEQ * DCH + d0;
    float*       yb = y + (size_t)b * LSEQ * DCH + d0;
    for (int l = tid; l < LSEQ; l += T) {
        float2 v  = src[l];
        float2 xv = *reinterpret_cast<const float2*>(xb + (size_t)l * DCH);
        float2 out = make_float2(xv.x + v.x * scale, xv.y + v.y * scale);
        *reinterpret_cast<float2*>(yb + (size_t)l * DCH) = out;
    }
}

// ---------------------------------------------------------------------------
// Per-mode complex block-diagonal MLP as batched GEMMs.
// Grid: (mode-tiles=33, n=8 blocks, b=8). CTA: 256 threads.
// Smem: W (2*96*96) + X tile (2*96*64) + O1 (2*96*64) = 172032 B.
// Each thread: 6 outputs x 4 modes x {re,im} = 48 fp32 accumulators.
// ---------------------------------------------------------------------------
__global__ __launch_bounds__(256) void mlp_kernel(const float* __restrict__ w1,
                                                  const float* __restrict__ b1,
                                                  const float* __restrict__ w2,
                                                  const float* __restrict__ b2) {
    float* Wr  = reinterpret_cast<float*>(smem_raw);   // [96][96], i-major, o contiguous
    float* Wi  = Wr + BS * BS;
    float* Xr  = Wi + BS * BS;                         // [96][64]
    float* Xi  = Xr + BS * MT;
    float* O1r = Xi + BS * MT;                         // [96][64]
    float* O1i = O1r + BS * MT;

    const int tid = threadIdx.x;
    const int n   = blockIdx.y;
    const int b   = blockIdx.z;
    const int m0  = blockIdx.x * MT;

    // stage W1 (layout w1[c][n][i][o])
    const float* w1r = w1 + (size_t)n * BS * BS;
    const float* w1i = w1 + (size_t)(NBLK + n) * BS * BS;
    for (int t = tid; t < BS * BS; t += 256) { Wr[t] = w1r[t]; Wi[t] = w1i[t]; }

    float* SrB = g_Sr + ((size_t)b * DCH + n * BS) * MP;
    float* SiB = g_Si + ((size_t)b * DCH + n * BS) * MP;
    for (int t = tid; t < BS * MT; t += 256) {
        int i = t / MT, mm = t % MT;
        int m = m0 + mm;
        float vr = 0.0f, vi = 0.0f;
        if (m < NMODES) { vr = SrB[(size_t)i * MP + m]; vi = SiB[(size_t)i * MP + m]; }
        Xr[t] = vr; Xi[t] = vi;
    }
    __syncthreads();

    const int mt = tid & 15;     // modes: mt, mt+16, mt+32, mt+48
    const int ot = tid >> 4;     // 0..15 -> outputs ot*6 .. ot*6+5

    float aR[6][4], aI[6][4];
    #pragma unroll
    for (int oo = 0; oo < 6; oo++) {
        float br_ = b1[(size_t)n * BS + ot * 6 + oo];
        float bi_ = b1[(size_t)(NBLK + n) * BS + ot * 6 + oo];
        #pragma unroll
        for (int j = 0; j < 4; j++) { aR[oo][j] = br_; aI[oo][j] = bi_; }
    }
    for (int i = 0; i < BS; i++) {
        float xr[4], xi[4];
        #pragma unroll
        for (int j = 0; j < 4; j++) {
            xr[j] = Xr[i * MT + mt + 16 * j];
            xi[j] = Xi[i * MT + mt + 16 * j];
        }
        #pragma unroll
        for (int oo = 0; oo < 6; oo++) {
            float wr = Wr[i * BS + ot * 6 + oo];
            float wi = Wi[i * BS + ot * 6 + oo];
            #pragma unroll
            for (int j = 0; j < 4; j++) {
                aR[oo][j] += wr * xr[j] - wi * xi[j];
                aI[oo][j] += wr * xi[j] + wi * xr[j];
            }
        }
    }
    __syncthreads();   // all reads of W1/X done before overwrite

    #pragma unroll
    for (int oo = 0; oo < 6; oo++)
        #pragma unroll
        for (int j = 0; j < 4; j++) {
            O1r[(ot * 6 + oo) * MT + mt + 16 * j] = fmaxf(aR[oo][j], 0.0f);
            O1i[(ot * 6 + oo) * MT + mt + 16 * j] = fmaxf(aI[oo][j], 0.0f);
        }
    // stage W2 (layout w2[c][n][o][j])
    const float* w2r = w2 + (size_t)n * BS * BS;
    const float* w2i = w2 + (size_t)(NBLK + n) * BS * BS;
    for (int t = tid; t < BS * BS; t += 256) { Wr[t] = w2r[t]; Wi[t] = w2i[t]; }
    __syncthreads();

    float cR[6][4], cI[6][4];
    #pragma unroll
    for (int oo = 0; oo < 6; oo++) {
        float br_ = b2[(size_t)n * BS + ot * 6 + oo];
        float bi_ = b2[(size_t)(NBLK + n) * BS + ot * 6 + oo];
        #pragma unroll
        for (int j = 0; j < 4; j++) { cR[oo][j] = br_; cI[oo][j] = bi_; }
    }
    for (int o = 0; o < BS; o++) {
        float pr[4], pi[4];
        #pragma unroll
        for (int j = 0; j < 4; j++) {
            pr[j] = O1r[o * MT + mt + 16 * j];
            pi[j] = O1i[o * MT + mt + 16 * j];
        }
        #pragma unroll
        for (int oo = 0; oo < 6; oo++) {
            float wr = Wr[o * BS + ot * 6 + oo];
            float wi = Wi[o * BS + ot * 6 + oo];
            #pragma unroll
            for (int j = 0; j < 4; j++) {
                cR[oo][j] += wr * pr[j] - wi * pi[j];
                cI[oo][j] += wr * pi[j] + wi * pr[j];
            }
        }
    }
    // softshrink + write back in place
    #pragma unroll
    for (int oo = 0; oo < 6; oo++) {
        int row = ot * 6 + oo;
        #pragma unroll
        for (int j = 0; j < 4; j++) {
            int m = m0 + mt + 16 * j;
            if (m < NMODES) {
                float vr = cR[oo][j];
                float tr = fabsf(vr) - LAMBDA;
                vr = tr > 0.0f ? copysignf(tr, vr) : 0.0f;
                float vi = cI[oo][j];
                float ti = fabsf(vi) - LAMBDA;
                vi = ti > 0.0f ? copysignf(ti, vi) : 0.0f;
                SrB[(size_t)row * MP + m] = vr;
                SiB[(size_t)row * MP + m] = vi;
            }
        }
    }
}

// ---------------------------------------------------------------------------
extern "C" void kernel_launch(void* const* d_in, const int* in_sizes, int n_in,
                              void* d_out, int out_size) {
    const float* x  = (const float*)d_in[0];
    const float* w1 = (const float*)d_in[1];
    const float* b1 = (const float*)d_in[2];
    const float* w2 = (const float*)d_in[3];
    const float* b2 = (const float*)d_in[4];
    float* y = (float*)d_out;

    const size_t fft_smem = (size_t)(2 * LSEQ + LSEQ / 2) * sizeof(float2);     // 81920
    const size_t mlp_smem = (size_t)(2 * BS * BS + 4 * BS * MT) * sizeof(float); // 172032

    cudaFuncSetAttribute(fwd_fft_kernel, cudaFuncAttributeMaxDynamicSharedMemorySize, (int)fft_smem);
    cudaFuncSetAttribute(inv_fft_kernel, cudaFuncAttributeMaxDynamicSharedMemorySize, (int)fft_smem);
    cudaFuncSetAttribute(mlp_kernel,     cudaFuncAttributeMaxDynamicSharedMemorySize, (int)mlp_smem);

    fwd_fft_kernel<<<NBATCH * DCH / 2, 256, fft_smem>>>(x);

    dim3 g((NMODES + MT - 1) / MT, NBLK, NBATCH);
    mlp_kernel<<<g, 256, mlp_smem>>>(w1, b1, w2, b2);

    inv_fft_kernel<<<NBATCH * DCH / 2, 256, fft_smem>>>(x, y);
}